// round 9
// baseline (speedup 1.0000x reference)
#include <cuda_runtime.h>
#include <cuda_fp16.h>
#include <cstdint>

// Shapes
#define S_ 256
#define BB 32
#define WMF 8192            // floats per (b,s) row, interleaved complex
#define PROW 4096           // floats per (b,s) row, planar
#define PLANE 33554432      // elems per plane (B*S*W*M)
#define NTHR 512
#define XP 136              // Xs row stride in halves (128 + 8 pad)
#define WP 264              // Ws row stride in halves (256 + 8 pad)

__device__ __align__(16) __half d_Wh[S_ * S_];   // diag(gain)*conn, fp16 [srow][k]
__device__ float2 d_tbl[S_ * 64];                // (decay*cos, decay*sin) per (s,w)
__device__ float2 d_scratch[PLANE];              // interleaved field buffer (268MB)

static __device__ __forceinline__ unsigned h2u(__half2 h) {
    return ((unsigned)__half_as_ushort(__high2half(h)) << 16) |
           (unsigned)__half_as_ushort(__low2half(h));
}

// ---------------- warp-level tensor helpers (sm_80 PTX, not 'a'-gated) ------
static __device__ __forceinline__ void ldsm4(uint32_t* r, uint32_t a) {
    asm volatile("ldmatrix.sync.aligned.m8n8.x4.shared.b16 {%0,%1,%2,%3}, [%4];"
                 : "=r"(r[0]), "=r"(r[1]), "=r"(r[2]), "=r"(r[3]) : "r"(a));
}
static __device__ __forceinline__ void ldsm4t(uint32_t* r, uint32_t a) {
    asm volatile("ldmatrix.sync.aligned.m8n8.x4.trans.shared.b16 {%0,%1,%2,%3}, [%4];"
                 : "=r"(r[0]), "=r"(r[1]), "=r"(r[2]), "=r"(r[3]) : "r"(a));
}
static __device__ __forceinline__ void mma16816(float* c, const uint32_t* a,
                                                uint32_t b0, uint32_t b1) {
    asm volatile(
        "mma.sync.aligned.m16n8k16.row.col.f32.f16.f16.f32 "
        "{%0,%1,%2,%3}, {%4,%5,%6,%7}, {%8,%9}, {%0,%1,%2,%3};"
        : "+f"(c[0]), "+f"(c[1]), "+f"(c[2]), "+f"(c[3])
        : "r"(a[0]), "r"(a[1]), "r"(a[2]), "r"(a[3]), "r"(b0), "r"(b1));
}

// ---------------------------------------------------------------------------
// Prep: dense fp16 W = diag(gain)*conn, fused phase/decay table.
// ---------------------------------------------------------------------------
__global__ void prep_kernel(const float* __restrict__ conn,
                            const float* __restrict__ gain,
                            const float* __restrict__ ww,
                            const float* __restrict__ disp) {
    int t = threadIdx.x;
    float g = gain[t];
    for (int j = 0; j < S_; j++)
        d_Wh[t * S_ + j] = __float2half(g * conn[t * S_ + j]);
    for (int i = t; i < S_ * 64; i += S_) {
        int w = i & 63;
        float phi = 0.1f * disp[w];
        float d = 0.95f * ww[i];
        d_tbl[i] = make_float2(d * cosf(phi), d * sinf(phi));
    }
}

// ---------------------------------------------------------------------------
// One fused step via mma.sync HMMA:
//   D[srow, scalar xcol] = sum_k W[srow][k] * X[k][xcol]   (A=W, B=X, TN-style)
//   epilogue: f = g*self(exact fp32) + D + bias; saturate; rotate*decay.
// CTA = (b, w). Xs panel [256 k][128 scalar cols] fp16 staged once;
// 4 chunks of 64 srows; warp-tile m16 x n32; 16 warps = 4m x 4n.
// C-frag: c0/c1 = (re,im) of one column -> shuffle-free epilogue.
// ---------------------------------------------------------------------------
template <bool PIN, bool POUT>
__global__ __launch_bounds__(NTHR, 2) void gemm_step(
    const float* __restrict__ inA,   // PIN: real plane; else interleaved base
    const float* __restrict__ inB,   // PIN: imag plane; else unused
    float* __restrict__ out,         // POUT: planar base; else interleaved base
    const float* __restrict__ gain,
    const float* __restrict__ bias) {
    extern __shared__ __half sm[];
    __half* Xs = sm;                 // [256][XP]
    __half* Ws = sm + S_ * XP;       // [64][WP]

    int tid = threadIdx.x, warp = tid >> 5, lane = tid & 31;
    int b = blockIdx.x >> 6, w = blockIdx.x & 63;
    size_t ibase = (size_t)b * ((size_t)S_ * WMF) + (size_t)w * 128;
    size_t pbase = (size_t)b * ((size_t)S_ * PROW) + (size_t)w * 64;

    // ---- stage X panel -> fp16 [k][scalar col] ----
    if (PIN) {
        for (int idx = tid; idx < S_ * 16; idx += NTHR) {
            int k = idx >> 4, q = idx & 15;
            float4 fr = *(const float4*)(inA + pbase + (size_t)k * PROW + 4 * q);
            float4 fi = *(const float4*)(inB + pbase + (size_t)k * PROW + 4 * q);
            uint4 pk = make_uint4(h2u(__floats2half2_rn(fr.x, fi.x)),
                                  h2u(__floats2half2_rn(fr.y, fi.y)),
                                  h2u(__floats2half2_rn(fr.z, fi.z)),
                                  h2u(__floats2half2_rn(fr.w, fi.w)));
            *(uint4*)(Xs + k * XP + 8 * q) = pk;
        }
    } else {
        for (int idx = tid; idx < S_ * 32; idx += NTHR) {
            int k = idx >> 5, q = idx & 31;
            float4 v = *(const float4*)(inA + ibase + (size_t)k * WMF + 4 * q);
            uint2 pk = make_uint2(h2u(__floats2half2_rn(v.x, v.y)),
                                  h2u(__floats2half2_rn(v.z, v.w)));
            *(uint2*)(Xs + k * XP + 4 * q) = pk;
        }
    }

    uint32_t sX = (uint32_t)__cvta_generic_to_shared(Xs);
    uint32_t sW = (uint32_t)__cvta_generic_to_shared(Ws);
    int mw = (warp & 3) * 16;            // m stripe within chunk
    int n0w = (warp >> 2) * 32;          // n stripe (scalar cols)
    int lr = (lane & 7) + ((lane >> 3) & 1) * 8;   // ldmatrix row-within-16
    int lc = (lane >> 4) * 8;                      // ldmatrix col group 0/8

    for (int chunk = 0; chunk < 4; chunk++) {
        __syncthreads();   // Xs staged (chunk 0) / prior chunk's reads done
        int srow0 = chunk * 64;
        for (int idx = tid; idx < 64 * 32; idx += NTHR) {
            int mr = idx >> 5, q = idx & 31;
            *(uint4*)(Ws + mr * WP + 8 * q) =
                *(const uint4*)(d_Wh + (srow0 + mr) * S_ + 8 * q);
        }
        __syncthreads();

        float acc[4][4];
        #pragma unroll
        for (int i = 0; i < 4; i++)
            for (int j = 0; j < 4; j++) acc[i][j] = 0.f;

        uint32_t aBase = sW + (uint32_t)(((mw + lr) * WP + lc) * 2);
        uint32_t bBase = sX + (uint32_t)((lr * XP + n0w + lc) * 2);
        #pragma unroll
        for (int ks = 0; ks < 16; ks++) {
            int k0 = ks * 16;
            uint32_t ra[4], rb[4], rb2[4];
            ldsm4(ra, aBase + (uint32_t)(k0 * 2));
            ldsm4t(rb, bBase + (uint32_t)(k0 * XP * 2));
            ldsm4t(rb2, bBase + (uint32_t)(k0 * XP * 2) + 32);
            mma16816(acc[0], ra, rb[0], rb[1]);
            mma16816(acc[1], ra, rb[2], rb[3]);
            mma16816(acc[2], ra, rb2[0], rb2[1]);
            mma16816(acc[3], ra, rb2[2], rb2[3]);
        }

        // ---- fused epilogue ----
        #pragma unroll
        for (int nf = 0; nf < 4; nf++) {
            int nsc = n0w + nf * 8 + 2 * (lane & 3);   // scalar col (re part)
            #pragma unroll
            for (int h = 0; h < 2; h++) {
                int srow = srow0 + mw + (lane >> 2) + h * 8;
                float cre = acc[nf][h * 2], cim = acc[nf][h * 2 + 1];
                float sre, sim;
                if (PIN) {
                    size_t pa = pbase + (size_t)srow * PROW + (nsc >> 1);
                    sre = __ldg(inA + pa);
                    sim = __ldg(inB + pa);
                } else {
                    float2 s = __ldg((const float2*)(inA + ibase +
                                                     (size_t)srow * WMF + nsc));
                    sre = s.x; sim = s.y;
                }
                float g = __ldg(gain + srow), bv = __ldg(bias + srow);
                float fre = fmaf(g, sre, cre + bv);   // bias -> real only
                float fim = fmaf(g, sim, cim);
                float inten = fmaf(fre, fre, fim * fim);
                float sc = __frcp_rn(fmaf(0.5f, inten, 1.0f));
                fre *= sc; fim *= sc;
                float2 dcs = d_tbl[(srow << 6) + w];
                float ore = fmaf(dcs.x, fre, -dcs.y * fim);
                float oim = fmaf(dcs.y, fre,  dcs.x * fim);
                if (POUT) {
                    size_t pa = pbase + (size_t)srow * PROW + (nsc >> 1);
                    out[pa] = ore;
                    out[(size_t)PLANE + pa] = oim;
                } else {
                    *(float2*)(out + ibase + (size_t)srow * WMF + nsc) =
                        make_float2(ore, oim);
                }
            }
        }
    }
}

// ---------------------------------------------------------------------------
// kernel_launch: prep + 4 HMMA steps, ping-pong scratch/d_out.
// ---------------------------------------------------------------------------
extern "C" void kernel_launch(void* const* d_in, const int* in_sizes, int n_in,
                              void* d_out, int out_size) {
    const float* fr   = (const float*)d_in[0];
    const float* fi   = (const float*)d_in[1];
    const float* conn = (const float*)d_in[2];
    const float* gain = (const float*)d_in[3];
    const float* bias = (const float*)d_in[4];
    const float* ww   = (const float*)d_in[5];
    const float* disp = (const float*)d_in[6];
    float* out = (float*)d_out;

    const int smem = (S_ * XP + 64 * WP) * 2;   // 103,424 B
    cudaFuncSetAttribute(gemm_step<true,  false>,
                         cudaFuncAttributeMaxDynamicSharedMemorySize, smem);
    cudaFuncSetAttribute(gemm_step<false, false>,
                         cudaFuncAttributeMaxDynamicSharedMemorySize, smem);
    cudaFuncSetAttribute(gemm_step<false, true>,
                         cudaFuncAttributeMaxDynamicSharedMemorySize, smem);

    float* scratch = nullptr;
    cudaGetSymbolAddress((void**)&scratch, d_scratch);

    prep_kernel<<<1, 256>>>(conn, gain, ww, disp);

    dim3 grid(BB * 64);   // 2048 CTAs: (b, w)
    gemm_step<true,  false><<<grid, NTHR, smem>>>(fr, fi, scratch, gain, bias);
    gemm_step<false, false><<<grid, NTHR, smem>>>(scratch, nullptr, out, gain, bias);
    gemm_step<false, false><<<grid, NTHR, smem>>>(out, nullptr, scratch, gain, bias);
    gemm_step<false, true ><<<grid, NTHR, smem>>>(scratch, nullptr, out, gain, bias);
}